// round 1
// baseline (speedup 1.0000x reference)
#include <cuda_runtime.h>

#define NFFT 1024

// Per-boundary XOR swizzles — each makes BOTH the producing-stage writes and
// the consuming-stage reads conflict-free (verified per-warp bank analysis).
__device__ __forceinline__ int sw0(int x){ return x ^ ((x & 0x60) >> 5); } // bits5-6 -> 0-1
__device__ __forceinline__ int sw1(int x){ return x ^ ((x & 0x60) >> 3); } // bits5-6 -> 2-3
__device__ __forceinline__ int sw2(int x){ return x ^ ((x & 0x40) >> 2); } // bit6   -> 4

// Inverse (sign = +i) radix-4 butterfly.
__device__ __forceinline__ void bfly4_inv(float vr[4], float vi[4]) {
    float t0r = vr[0] + vr[2], t0i = vi[0] + vi[2];
    float t1r = vr[0] - vr[2], t1i = vi[0] - vi[2];
    float t2r = vr[1] + vr[3], t2i = vi[1] + vi[3];
    float t3r = vr[1] - vr[3], t3i = vi[1] - vi[3];
    vr[0] = t0r + t2r; vi[0] = t0i + t2i;
    vr[2] = t0r - t2r; vi[2] = t0i - t2i;
    // b1 = t1 + i*t3 ; b3 = t1 - i*t3
    vr[1] = t1r - t3i; vi[1] = t1i + t3r;
    vr[3] = t1r + t3i; vi[3] = t1i - t3r;
}

// Inverse twiddles: v[r] *= exp(+i * 2*pi * r * (j mod NS) / (4*NS))
template<int NS>
__device__ __forceinline__ void twiddle_inv(int j, float vr[4], float vi[4]) {
    const int m = j & (NS - 1);
    const float ang = (6.2831853071795864769f / (4.0f * (float)NS)) * (float)m;
    float c1, s1;
    __sincosf(ang, &s1, &c1);
    { float tr = vr[1]*c1 - vi[1]*s1; vi[1] = vr[1]*s1 + vi[1]*c1; vr[1] = tr; }
    float c2 = c1*c1 - s1*s1, s2 = 2.0f*c1*s1;
    { float tr = vr[2]*c2 - vi[2]*s2; vi[2] = vr[2]*s2 + vi[2]*c2; vr[2] = tr; }
    float c3 = c1*c2 - s1*s2, s3 = c1*s2 + s1*c2;
    { float tr = vr[3]*c3 - vi[3]*s3; vi[3] = vr[3]*s3 + vi[3]*c3; vr[3] = tr; }
}

// One 1024-point complex inverse FFT per CTA (radix-4 Stockham, natural order
// in and out). 256 threads, 4 complex points per thread.
__global__ void __launch_bounds__(256, 8)
ifft1024_kernel(const float* __restrict__ gre, const float* __restrict__ gim,
                float* __restrict__ outr, float* __restrict__ outi)
{
    __shared__ float sr[NFFT];
    __shared__ float si[NFFT];
    const int j = threadIdx.x;
    const size_t base = (size_t)blockIdx.x * NFFT;

    float vr[4], vi[4];

    // ---- stage 0 (Ns=1): global -> regs, no twiddle ----
#pragma unroll
    for (int r = 0; r < 4; ++r) {
        vr[r] = gre[base + j + 256*r];
        vi[r] = gim[base + j + 256*r];
    }
    bfly4_inv(vr, vi);
#pragma unroll
    for (int r = 0; r < 4; ++r) { int a = sw0(4*j + r); sr[a] = vr[r]; si[a] = vi[r]; }
    __syncthreads();

    // ---- stage 1 (Ns=4) ----
#pragma unroll
    for (int r = 0; r < 4; ++r) { int a = sw0(j + 256*r); vr[r] = sr[a]; vi[r] = si[a]; }
    twiddle_inv<4>(j, vr, vi);
    bfly4_inv(vr, vi);
    __syncthreads();
    {
        const int idxD = ((j >> 2) << 4) | (j & 3);
#pragma unroll
        for (int r = 0; r < 4; ++r) { int a = sw1(idxD + 4*r); sr[a] = vr[r]; si[a] = vi[r]; }
    }
    __syncthreads();

    // ---- stage 2 (Ns=16) ----
#pragma unroll
    for (int r = 0; r < 4; ++r) { int a = sw1(j + 256*r); vr[r] = sr[a]; vi[r] = si[a]; }
    twiddle_inv<16>(j, vr, vi);
    bfly4_inv(vr, vi);
    __syncthreads();
    {
        const int idxD = ((j >> 4) << 6) | (j & 15);
#pragma unroll
        for (int r = 0; r < 4; ++r) { int a = sw2(idxD + 16*r); sr[a] = vr[r]; si[a] = vi[r]; }
    }
    __syncthreads();

    // ---- stage 3 (Ns=64) ----
#pragma unroll
    for (int r = 0; r < 4; ++r) { int a = sw2(j + 256*r); vr[r] = sr[a]; vi[r] = si[a]; }
    twiddle_inv<64>(j, vr, vi);
    bfly4_inv(vr, vi);
    __syncthreads();
    {
        const int idxD = ((j >> 6) << 8) | (j & 63);
#pragma unroll
        for (int r = 0; r < 4; ++r) { int a = idxD + 64*r; sr[a] = vr[r]; si[a] = vi[r]; }
    }
    __syncthreads();

    // ---- stage 4 (Ns=256): regs -> global, natural order ----
#pragma unroll
    for (int r = 0; r < 4; ++r) { vr[r] = sr[j + 256*r]; vi[r] = si[j + 256*r]; }
    twiddle_inv<256>(j, vr, vi);
    bfly4_inv(vr, vi);

    const float scale = 1.0f / 1024.0f;  // ifft normalization
#pragma unroll
    for (int r = 0; r < 4; ++r) {
        outr[base + j + 256*r] = vr[r] * scale;
        outi[base + j + 256*r] = vi[r] * scale;
    }
}

extern "C" void kernel_launch(void* const* d_in, const int* in_sizes, int n_in,
                              void* d_out, int out_size) {
    // Inputs: re (8,4096,1024) f32, im (8,4096,1024) f32, fft_real, fft_imag (unused:
    // they encode exactly np.fft.ifft, which we compute directly).
    const float* re = (const float*)d_in[0];
    const float* im = (const float*)d_in[1];
    float* out = (float*)d_out;
    const int half = out_size / 2;           // y_real then y_imag, concatenated
    const int nrows = in_sizes[0] / NFFT;    // 32768

    ifft1024_kernel<<<nrows, 256>>>(re, im, out, out + half);
}

// round 2
// speedup vs baseline: 1.0800x; 1.0800x over previous
#include <cuda_runtime.h>

typedef unsigned long long u64;
#define NFFT 1024

// ---- packed f32x2 helpers (sm_103a) ----
__device__ __forceinline__ u64 pk(float x, float y) {
    u64 u; asm("mov.b64 %0,{%1,%2};" : "=l"(u) : "f"(x), "f"(y)); return u;
}
__device__ __forceinline__ void upk(u64 u, float& x, float& y) {
    asm("mov.b64 {%0,%1},%2;" : "=f"(x), "=f"(y) : "l"(u));
}
__device__ __forceinline__ u64 padd(u64 a, u64 b) {
    u64 d; asm("add.rn.f32x2 %0,%1,%2;" : "=l"(d) : "l"(a), "l"(b)); return d;
}
__device__ __forceinline__ u64 pmul(u64 a, u64 b) {
    u64 d; asm("mul.rn.f32x2 %0,%1,%2;" : "=l"(d) : "l"(a), "l"(b)); return d;
}
__device__ __forceinline__ u64 pfma(u64 a, u64 b, u64 c) {
    u64 d; asm("fma.rn.f32x2 %0,%1,%2,%3;" : "=l"(d) : "l"(a), "l"(b), "l"(c)); return d;
}
__device__ __forceinline__ u64 psub(u64 a, u64 b) {  // a - b  (fma: b*(-1)+a)
    const u64 NEG1 = 0xBF800000BF800000ULL;
    return pfma(b, NEG1, a);
}

// ---- boundary swizzles for 8-byte shared banking (bank-pair = idx mod 16) ----
__device__ __forceinline__ int s0(int x) { return x ^ ((x >> 4) & 3); }    // bits4-5 -> 0-1
__device__ __forceinline__ int s1(int x) { return x ^ ((x >> 2) & 0xC); }  // bits4-5 -> 2-3

// Inverse (sign = +i) radix-4 butterfly on packed complex values.
__device__ __forceinline__ void bfly4_inv(u64 v[4]) {
    u64 t0 = padd(v[0], v[2]);
    u64 t1 = psub(v[0], v[2]);
    u64 t2 = padd(v[1], v[3]);
    u64 t3 = psub(v[1], v[3]);
    v[0] = padd(t0, t2);
    v[2] = psub(t0, t2);
    float tr, ti; upk(t3, tr, ti);
    u64 w = pk(-ti, tr);          // i * t3
    v[1] = padd(t1, w);           // t1 + i*t3
    v[3] = psub(t1, w);           // t1 - i*t3
}

// Inverse twiddles: v[r] *= exp(+i * 2*pi * r * (j mod NS) / (4*NS))
template<int NS>
__device__ __forceinline__ void twiddle_inv(int j, u64 v[4]) {
    const int m = j & (NS - 1);
    const float ang = (6.2831853071795864769f / (4.0f * (float)NS)) * (float)m;
    float c1, s1v;
    __sincosf(ang, &s1v, &c1);
    float c2 = c1 * c1 - s1v * s1v, s2 = 2.0f * c1 * s1v;
    float c3 = c1 * c2 - s1v * s2,  s3 = c1 * s2 + s1v * c2;
    float xr, xi;
    upk(v[1], xr, xi); v[1] = pk(xr * c1 - xi * s1v, xr * s1v + xi * c1);
    upk(v[2], xr, xi); v[2] = pk(xr * c2 - xi * s2,  xr * s2  + xi * c2);
    upk(v[3], xr, xi); v[3] = pk(xr * c3 - xi * s3,  xr * s3  + xi * c3);
}

// One 1024-point complex inverse FFT per CTA (radix-4 Stockham, natural order
// in and out). 256 threads, 4 complex points per thread. Double-buffered
// packed-complex shared memory, conflict-free for 8-byte banking.
__global__ void __launch_bounds__(256, 6)
ifft1024_kernel(const float* __restrict__ gre, const float* __restrict__ gim,
                float* __restrict__ outr, float* __restrict__ outi)
{
    __shared__ u64 sA[NFFT];
    __shared__ u64 sB[NFFT];
    const int j = threadIdx.x;
    const size_t base = (size_t)blockIdx.x * NFFT;

    u64 v[4];

    // ---- stage 0 (Ns=1): global -> regs, no twiddle ----
#pragma unroll
    for (int r = 0; r < 4; ++r)
        v[r] = pk(gre[base + j + 256 * r], gim[base + j + 256 * r]);
    bfly4_inv(v);
#pragma unroll
    for (int r = 0; r < 4; ++r) sA[s0(4 * j + r)] = v[r];
    __syncthreads();

    // ---- stage 1 (Ns=4) ----
#pragma unroll
    for (int r = 0; r < 4; ++r) v[r] = sA[s0(j + 256 * r)];
    twiddle_inv<4>(j, v);
    bfly4_inv(v);
    {
        const int d = ((j >> 2) << 4) | (j & 3);
#pragma unroll
        for (int r = 0; r < 4; ++r) sB[s1(d + 4 * r)] = v[r];
    }
    __syncthreads();

    // ---- stage 2 (Ns=16) ----
#pragma unroll
    for (int r = 0; r < 4; ++r) v[r] = sB[s1(j + 256 * r)];
    twiddle_inv<16>(j, v);
    bfly4_inv(v);
    {
        const int d = ((j >> 4) << 6) | (j & 15);
#pragma unroll
        for (int r = 0; r < 4; ++r) sA[d + 16 * r] = v[r];   // bits0-3 = j&15: conflict-free
    }
    __syncthreads();

    // ---- stage 3 (Ns=64) ----
#pragma unroll
    for (int r = 0; r < 4; ++r) v[r] = sA[j + 256 * r];
    twiddle_inv<64>(j, v);
    bfly4_inv(v);
    {
        const int d = ((j >> 6) << 8) | (j & 63);
#pragma unroll
        for (int r = 0; r < 4; ++r) sB[d + 64 * r] = v[r];    // bits0-3 = j&15: conflict-free
    }
    __syncthreads();

    // ---- stage 4 (Ns=256): regs -> global, natural order ----
#pragma unroll
    for (int r = 0; r < 4; ++r) v[r] = sB[j + 256 * r];
    twiddle_inv<256>(j, v);
    bfly4_inv(v);

    const u64 SC = 0x3A8000003A800000ULL;  // packed (1/1024, 1/1024)
#pragma unroll
    for (int r = 0; r < 4; ++r) {
        u64 y = pmul(v[r], SC);
        float yr, yi; upk(y, yr, yi);
        outr[base + j + 256 * r] = yr;
        outi[base + j + 256 * r] = yi;
    }
}

extern "C" void kernel_launch(void* const* d_in, const int* in_sizes, int n_in,
                              void* d_out, int out_size) {
    // Inputs: re (8,4096,1024) f32, im (8,4096,1024) f32, fft_real, fft_imag
    // (the matrices encode exactly np.fft.ifft, which we compute directly).
    const float* re = (const float*)d_in[0];
    const float* im = (const float*)d_in[1];
    float* out = (float*)d_out;
    const int half = out_size / 2;           // y_real then y_imag, concatenated
    const int nrows = in_sizes[0] / NFFT;    // 32768

    ifft1024_kernel<<<nrows, 256>>>(re, im, out, out + half);
}

// round 3
// speedup vs baseline: 1.3283x; 1.2299x over previous
#include <cuda_runtime.h>

typedef unsigned long long u64;
#define NFFT 1024
#define TWO_PI 6.2831853071795864769f

// ---- packed f32x2 helpers (sm_103a) ----
__device__ __forceinline__ u64 pk(float x, float y) {
    u64 u; asm("mov.b64 %0,{%1,%2};" : "=l"(u) : "f"(x), "f"(y)); return u;
}
__device__ __forceinline__ void upk(u64 u, float& x, float& y) {
    asm("mov.b64 {%0,%1},%2;" : "=f"(x), "=f"(y) : "l"(u));
}
__device__ __forceinline__ u64 padd(u64 a, u64 b) {
    u64 d; asm("add.rn.f32x2 %0,%1,%2;" : "=l"(d) : "l"(a), "l"(b)); return d;
}
__device__ __forceinline__ u64 pfma(u64 a, u64 b, u64 c) {
    u64 d; asm("fma.rn.f32x2 %0,%1,%2,%3;" : "=l"(d) : "l"(a), "l"(b), "l"(c)); return d;
}
__device__ __forceinline__ u64 psub(u64 a, u64 b) {  // a - b
    const u64 NEG1 = 0xBF800000BF800000ULL;
    return pfma(b, NEG1, a);
}
// complex multiply (packed) by (br, bi)
__device__ __forceinline__ u64 cmulc(u64 a, float br, float bi) {
    float ar, ai; upk(a, ar, ai);
    return pk(fmaf(-ai, bi, ar * br), fmaf(ar, bi, ai * br));
}
__device__ __forceinline__ u64 cmul(u64 a, u64 b) {
    float br, bi; upk(b, br, bi);
    return cmulc(a, br, bi);
}
__device__ __forceinline__ u64 muli(u64 a) {  // a * i
    float ar, ai; upk(a, ar, ai);
    return pk(-ai, ar);
}

// Inverse (sign = +i) radix-4 butterfly on packed complex values.
__device__ __forceinline__ void bfly4_inv(u64 v[4]) {
    u64 t0 = padd(v[0], v[2]);
    u64 t1 = psub(v[0], v[2]);
    u64 t2 = padd(v[1], v[3]);
    u64 t3 = psub(v[1], v[3]);
    v[0] = padd(t0, t2);
    v[2] = psub(t0, t2);
    u64 w = muli(t3);
    v[1] = padd(t1, w);
    v[3] = psub(t1, w);
}

// In-register inverse 16-point DFT: v[n] -> X[k], natural order in and out.
// Split 16 = 4*4: n = 4*n1 + n2, k = k1 + 4*k2.
__device__ __forceinline__ void dft16_inv(u64 v[16]) {
    const float C  = 0.70710678118654752f;   // cos(pi/4)
    const float C1 = 0.92387953251128676f;   // cos(pi/8)
    const float S1 = 0.38268343236508977f;   // sin(pi/8)
    u64 a[16];  // a[k1*4 + n2]
#pragma unroll
    for (int n2 = 0; n2 < 4; ++n2) {
        u64 t[4] = { v[n2], v[n2 + 4], v[n2 + 8], v[n2 + 12] };
        bfly4_inv(t);
        a[0 + n2] = t[0]; a[4 + n2] = t[1]; a[8 + n2] = t[2]; a[12 + n2] = t[3];
    }
    // twiddles a[k1][n2] *= W16^{n2*k1}  (inverse: positive exponent)
    a[4 + 1]  = cmulc(a[4 + 1],  C1,  S1);   // W^1
    a[4 + 2]  = cmulc(a[4 + 2],  C,   C);    // W^2
    a[4 + 3]  = cmulc(a[4 + 3],  S1,  C1);   // W^3
    a[8 + 1]  = cmulc(a[8 + 1],  C,   C);    // W^2
    a[8 + 2]  = muli (a[8 + 2]);             // W^4 = i
    a[8 + 3]  = cmulc(a[8 + 3], -C,   C);    // W^6
    a[12 + 1] = cmulc(a[12 + 1],  S1,  C1);  // W^3
    a[12 + 2] = cmulc(a[12 + 2], -C,   C);   // W^6
    a[12 + 3] = cmulc(a[12 + 3], -C1, -S1);  // W^9
#pragma unroll
    for (int k1 = 0; k1 < 4; ++k1) {
        u64 t[4] = { a[k1 * 4 + 0], a[k1 * 4 + 1], a[k1 * 4 + 2], a[k1 * 4 + 3] };
        bfly4_inv(t);
        v[k1] = t[0]; v[k1 + 4] = t[1]; v[k1 + 8] = t[2]; v[k1 + 12] = t[3];
    }
}

// 1024-pt inverse FFT: N = 16*64, n = 64*n1 + n2, k = k1 + 16*k2.
// Phase A (thread t = n2): A[k1] = DFT16_{n1}(x[64n1+t]);  z = A * W1024^{t*k1}
// Phase B (thread = (k1, q)): 64 = 16*4, n2 = 4m+q, k2 = c + 16d:
//   B[c] = DFT16_m(z[k1, 4m+q]);  u = B * W64^{q*c}
// Phase C: X[k1 + 16c + 256d] = radix4_q(u).    2 rows per 128-thread CTA.
__global__ void __launch_bounds__(128, 6)
ifft1024_kernel(const float* __restrict__ gre, const float* __restrict__ gim,
                float* __restrict__ outr, float* __restrict__ outi)
{
    __shared__ u64 sh[2][NFFT];
    const int tid = threadIdx.x;
    const int rowl = tid >> 6;        // 0 / 1
    const int t = tid & 63;
    u64* s = sh[rowl];
    const size_t base = ((size_t)blockIdx.x * 2 + rowl) * NFFT;

    u64 v[16];

    // ---- Phase A ----
#pragma unroll
    for (int n1 = 0; n1 < 16; ++n1)
        v[n1] = pk(gre[base + 64 * n1 + t], gim[base + 64 * n1 + t]);
    dft16_inv(v);
    {
        const float ang = (TWO_PI / 1024.0f) * (float)t;
#pragma unroll
        for (int k1 = 1; k1 < 16; ++k1) {
            float sn, cs;
            __sincosf(ang * (float)k1, &sn, &cs);
            v[k1] = cmulc(v[k1], cs, sn);
        }
        // store: phys = (t>>4)<<8 | k1<<4 | ((t&15) ^ ((k1&3)<<2))  — conflict-free
        const int hi = (t >> 4) << 8;
        const int lo = t & 15;
#pragma unroll
        for (int k1 = 0; k1 < 16; ++k1)
            s[hi | (k1 << 4) | (lo ^ ((k1 & 3) << 2))] = v[k1];
    }
    __syncthreads();

    // ---- Phase B ----
    {
        const int k1 = t >> 2, q = t & 3;
#pragma unroll
        for (int m = 0; m < 16; ++m) {
            const int n2 = 4 * m + q;
            const int phys = ((n2 >> 4) << 8) | (k1 << 4) | ((n2 & 15) ^ ((k1 & 3) << 2));
            v[m] = s[phys];
        }
        dft16_inv(v);
        const float ang = (TWO_PI / 64.0f) * (float)q;
#pragma unroll
        for (int c = 1; c < 16; ++c) {
            float sn, cs;
            __sincosf(ang * (float)c, &sn, &cs);
            v[c] = cmulc(v[c], cs, sn);
        }
        __syncthreads();   // all reads of exchange-1 complete before reuse
        // store at idx = k1 + 16c + 256q, swizzle idx ^ ((idx>>8)&3)<<2 — conflict-free
#pragma unroll
        for (int c = 0; c < 16; ++c) {
            const int idx = k1 + 16 * c + 256 * q;
            s[idx ^ (q << 2)] = v[c];
        }
    }
    __syncthreads();

    // ---- Phase C: final radix-4 across q, coalesced stores ----
    {
        const float SCALE = 1.0f / 1024.0f;
#pragma unroll
        for (int jj = 0; jj < 4; ++jj) {
            const int p = t + 64 * jj;     // p = k1 + 16*c  in [0,256)
            u64 u[4];
#pragma unroll
            for (int q = 0; q < 4; ++q) {
                const int idx = p + 256 * q;
                u[q] = s[idx ^ (q << 2)];
            }
            bfly4_inv(u);
#pragma unroll
            for (int d = 0; d < 4; ++d) {
                float yr, yi; upk(u[d], yr, yi);
                outr[base + p + 256 * d] = yr * SCALE;
                outi[base + p + 256 * d] = yi * SCALE;
            }
        }
    }
}

extern "C" void kernel_launch(void* const* d_in, const int* in_sizes, int n_in,
                              void* d_out, int out_size) {
    const float* re = (const float*)d_in[0];
    const float* im = (const float*)d_in[1];
    float* out = (float*)d_out;
    const int half = out_size / 2;           // y_real then y_imag, concatenated
    const int nrows = in_sizes[0] / NFFT;    // 32768
    ifft1024_kernel<<<nrows / 2, 128>>>(re, im, out, out + half);
}